// round 1
// baseline (speedup 1.0000x reference)
#include <cuda_runtime.h>
#include <math.h>
#include <stdint.h>

#define KDIM 256
#define DDIM 128
#define BB 4
#define TT 1024
#define NG 8
#define NITER 100
#define NSQ 20
#define LAMBDA 0.01f
#define REGV 0.01f
#define NTOT (BB*KDIM*TT)

// ---------------- device scratch (no allocations allowed) ----------------
__device__ float g_DtD[KDIM*KDIM];
__device__ float g_At[KDIM*KDIM];          // A^T, A = I - DtD/L
__device__ float g_M[2][KDIM*KDIM];        // ping-pong for matrix squaring
__device__ float g_scale[NSQ+1];           // max-abs per squaring step
__device__ float g_Linv, g_lambd;
__device__ float g_DtY[NTOT];
__device__ float g_x[NTOT];
__device__ float g_mx[NTOT];
__device__ float g_l1[NTOT];
__device__ float g_gsum[NITER][NG];        // per-iteration group sum-of-squares

__device__ __forceinline__ void atomicMaxPosF(float* a, float v){
    // valid for non-negative floats (monotone bit pattern)
    atomicMax((int*)a, __float_as_int(v));
}

// ---------------- init: copy x0 -> x, mx; zero gsum + scales ----------------
__global__ void k_init(const float* __restrict__ x0){
    int i = blockIdx.x*blockDim.x + threadIdx.x;
    if (i < NTOT){ float v = x0[i]; g_x[i]=v; g_mx[i]=v; }
    if (i < NITER*NG) ((float*)g_gsum)[i]=0.f;
    if (i <= NSQ) g_scale[i]=0.f;
}

// ---------------- DtD = D^T D  (block = row i, thread = col j) ----------------
__global__ void k_dtd(const float* __restrict__ Dict){
    int i=blockIdx.x, j=threadIdx.x;
    float acc=0.f;
    #pragma unroll 8
    for(int d=0; d<DDIM; d++)
        acc += Dict[d*KDIM+i]*Dict[d*KDIM+j];
    g_DtD[i*KDIM+j]=acc;
    float m=fabsf(acc);
    #pragma unroll
    for(int o=16;o>0;o>>=1) m=fmaxf(m,__shfl_xor_sync(0xffffffffu,m,o));
    __shared__ float sm[8];
    if((j&31)==0) sm[j>>5]=m;
    __syncthreads();
    if(j==0){
        float mm=sm[0];
        #pragma unroll
        for(int w=1;w<8;w++) mm=fmaxf(mm,sm[w]);
        atomicMaxPosF(&g_scale[0], mm);
    }
}

// ---------------- one matrix squaring step (normalized) ----------------
__global__ void k_square(int step){
    const float* __restrict__ in = (step==0)? g_DtD : g_M[(step-1)&1];
    float* __restrict__ out = g_M[step&1];
    __shared__ float sh[KDIM];
    int i=blockIdx.x, j=threadIdx.x;
    sh[j]=in[i*KDIM+j];
    __syncthreads();
    float inv = 1.0f/g_scale[step];
    float acc=0.f;
    #pragma unroll 8
    for(int p=0;p<KDIM;p++) acc += sh[p]*in[p*KDIM+j];
    acc *= inv*inv;
    out[i*KDIM+j]=acc;
    float m=fabsf(acc);
    #pragma unroll
    for(int o=16;o>0;o>>=1) m=fmaxf(m,__shfl_xor_sync(0xffffffffu,m,o));
    __shared__ float sm[8];
    if((j&31)==0) sm[j>>5]=m;
    __syncthreads();
    if(j==0){
        float mm=sm[0];
        #pragma unroll
        for(int w=1;w<8;w++) mm=fmaxf(mm,sm[w]);
        atomicMaxPosF(&g_scale[step+1], mm);
    }
}

// ---------------- Rayleigh quotient: L = v^T DtD v / v^T v ----------------
__global__ void k_rayleigh(int bufidx){
    const float* __restrict__ Mf = g_M[bufidx];
    __shared__ float v[KDIM];
    __shared__ float red[KDIM];
    __shared__ int rid[KDIM];
    int j=threadIdx.x;
    // pick column with largest diagonal of the (near rank-1) matrix
    red[j]=Mf[j*KDIM+j]; rid[j]=j;
    __syncthreads();
    for(int s=KDIM/2;s>0;s>>=1){
        if(j<s && red[j+s]>red[j]){ red[j]=red[j+s]; rid[j]=rid[j+s]; }
        __syncthreads();
    }
    int jstar=rid[0];
    __syncthreads();
    v[j]=Mf[j*KDIM+jstar];
    __syncthreads();
    float u=0.f;
    #pragma unroll 8
    for(int p=0;p<KDIM;p++) u += g_DtD[j*KDIM+p]*v[p];
    float num=u*v[j], den=v[j]*v[j];
    red[j]=num; __syncthreads();
    for(int s=KDIM/2;s>0;s>>=1){ if(j<s) red[j]+=red[j+s]; __syncthreads(); }
    float NUM=red[0]; __syncthreads();
    red[j]=den; __syncthreads();
    for(int s=KDIM/2;s>0;s>>=1){ if(j<s) red[j]+=red[j+s]; __syncthreads(); }
    if(j==0){
        float L = NUM/red[0];
        g_Linv = 1.0f/L;
        g_lambd = LAMBDA/L;
    }
}

// ---------------- A^T build (transposed so GEMM tile loads coalesce) ----------------
__global__ void k_buildAt(){
    int i=blockIdx.x, j=threadIdx.x;
    float a = ((i==j)?1.f:0.f) - g_DtD[i*KDIM+j]*g_Linv;
    g_At[j*KDIM+i]=a;
}

// ---------------- DtY[b,k,t] = sum_d D[d,k] * inp[b,d,t] ----------------
__global__ void k_dty(const float* __restrict__ Dict, const float* __restrict__ inp){
    __shared__ float As[16][64];
    __shared__ float Bs[16][64];
    int tbase=blockIdx.x<<6, kbase=blockIdx.y<<6, b=blockIdx.z;
    int tid=threadIdx.x, tx=tid&15, ty=tid>>4;
    float acc[4][4];
    #pragma unroll
    for(int i=0;i<4;i++){
        #pragma unroll
        for(int q=0;q<4;q++) acc[i][q]=0.f;
    }
    for(int d0=0; d0<DDIM; d0+=16){
        #pragma unroll
        for(int r=0;r<4;r++){
            int e=tid + (r<<8);
            int dd=e>>6, cc=e&63;
            As[dd][cc]=Dict[(d0+dd)*KDIM + kbase+cc];
            Bs[dd][cc]=inp[(b*DDIM + d0+dd)*TT + tbase+cc];
        }
        __syncthreads();
        #pragma unroll
        for(int p=0;p<16;p++){
            float4 a=*(const float4*)&As[p][ty<<2];
            float4 bv=*(const float4*)&Bs[p][tx<<2];
            acc[0][0]+=a.x*bv.x; acc[0][1]+=a.x*bv.y; acc[0][2]+=a.x*bv.z; acc[0][3]+=a.x*bv.w;
            acc[1][0]+=a.y*bv.x; acc[1][1]+=a.y*bv.y; acc[1][2]+=a.y*bv.z; acc[1][3]+=a.y*bv.w;
            acc[2][0]+=a.z*bv.x; acc[2][1]+=a.z*bv.y; acc[2][2]+=a.z*bv.z; acc[2][3]+=a.z*bv.w;
            acc[3][0]+=a.w*bv.x; acc[3][1]+=a.w*bv.y; acc[3][2]+=a.w*bv.z; acc[3][3]+=a.w*bv.w;
        }
        __syncthreads();
    }
    #pragma unroll
    for(int i=0;i<4;i++){
        int kg=kbase+(ty<<2)+i;
        float4 o=make_float4(acc[i][0],acc[i][1],acc[i][2],acc[i][3]);
        *(float4*)&g_DtY[(b*KDIM+kg)*TT + tbase + (tx<<2)] = o;
    }
}

// ------- per-iteration K1: Ay = A@mx, fused l1-prox, group sumsq reduction -------
__global__ void k_gemm_prox(int iter){
    __shared__ float As[16][64];
    __shared__ float Bs[16][64];
    __shared__ float sred[8];
    int tbase=blockIdx.x<<6, kbase=blockIdx.y<<6, b=blockIdx.z;
    int tid=threadIdx.x, tx=tid&15, ty=tid>>4;
    float acc[4][4];
    #pragma unroll
    for(int i=0;i<4;i++){
        #pragma unroll
        for(int q=0;q<4;q++) acc[i][q]=0.f;
    }
    for(int j0=0;j0<KDIM;j0+=16){
        #pragma unroll
        for(int r=0;r<4;r++){
            int e=tid+(r<<8);
            int jj=e>>6, cc=e&63;
            As[jj][cc]=g_At[(j0+jj)*KDIM + kbase+cc];
            Bs[jj][cc]=g_mx[(b*KDIM + j0+jj)*TT + tbase+cc];
        }
        __syncthreads();
        #pragma unroll
        for(int p=0;p<16;p++){
            float4 a=*(const float4*)&As[p][ty<<2];
            float4 bv=*(const float4*)&Bs[p][tx<<2];
            acc[0][0]+=a.x*bv.x; acc[0][1]+=a.x*bv.y; acc[0][2]+=a.x*bv.z; acc[0][3]+=a.x*bv.w;
            acc[1][0]+=a.y*bv.x; acc[1][1]+=a.y*bv.y; acc[1][2]+=a.y*bv.z; acc[1][3]+=a.y*bv.w;
            acc[2][0]+=a.z*bv.x; acc[2][1]+=a.z*bv.y; acc[2][2]+=a.z*bv.z; acc[2][3]+=a.z*bv.w;
            acc[3][0]+=a.w*bv.x; acc[3][1]+=a.w*bv.y; acc[3][2]+=a.w*bv.z; acc[3][3]+=a.w*bv.w;
        }
        __syncthreads();
    }
    float Linv=g_Linv, lam=g_lambd;
    float ssq=0.f;
    #pragma unroll
    for(int i=0;i<4;i++){
        int kg=kbase+(ty<<2)+i;
        int base=(b*KDIM+kg)*TT + tbase + (tx<<2);
        float4 dty=*(const float4*)&g_DtY[base];
        float s0=acc[i][0]+dty.x*Linv;
        float s1=acc[i][1]+dty.y*Linv;
        float s2=acc[i][2]+dty.z*Linv;
        float s3=acc[i][3]+dty.w*Linv;
        float v0=fmaxf(s0-lam,0.f)+fminf(s0+lam,0.f);
        float v1=fmaxf(s1-lam,0.f)+fminf(s1+lam,0.f);
        float v2=fmaxf(s2-lam,0.f)+fminf(s2+lam,0.f);
        float v3=fmaxf(s3-lam,0.f)+fminf(s3+lam,0.f);
        *(float4*)&g_l1[base]=make_float4(v0,v1,v2,v3);
        ssq += v0*v0+v1*v1+v2*v2+v3*v3;
    }
    // warps 0..3 cover k in [kbase,kbase+32) (group kbase/32); warps 4..7 the next group
    #pragma unroll
    for(int o=16;o>0;o>>=1) ssq += __shfl_xor_sync(0xffffffffu, ssq, o);
    if((tid&31)==0) sred[tid>>5]=ssq;
    __syncthreads();
    if(tid==0)   atomicAdd(&g_gsum[iter][(kbase>>5)  ], sred[0]+sred[1]+sred[2]+sred[3]);
    if(tid==128) atomicAdd(&g_gsum[iter][(kbase>>5)+1], sred[4]+sred[5]+sred[6]+sred[7]);
}

// ------- per-iteration K2: group-L2 scale + momentum update -------
__global__ void k_update(int iter, float coef, float* __restrict__ dout, int last){
    int i = blockIdx.x*blockDim.x + threadIdx.x;   // 0..NTOT/4-1
    int idx = i<<2;
    int k = (idx>>10) & (KDIM-1);
    int g = k>>5;
    float s = g_gsum[iter][g];
    float scale = (s>0.f)? fmaxf(0.f, 1.f - REGV/sqrtf(s)) : 0.f;
    float4 l1 = *(const float4*)&g_l1[idx];
    float4 xo = *(const float4*)&g_x[idx];
    float4 nx, nmx;
    nx.x=l1.x*scale; nx.y=l1.y*scale; nx.z=l1.z*scale; nx.w=l1.w*scale;
    nmx.x = nx.x + (nx.x-xo.x)*coef;
    nmx.y = nx.y + (nx.y-xo.y)*coef;
    nmx.z = nx.z + (nx.z-xo.z)*coef;
    nmx.w = nx.w + (nx.w-xo.w)*coef;
    float* xp = last? dout : g_x;
    *(float4*)&xp[idx]=nx;
    *(float4*)&g_mx[idx]=nmx;
}

// ---------------- host launcher (graph-capturable: kernels only) ----------------
extern "C" void kernel_launch(void* const* d_in, const int* in_sizes, int n_in,
                              void* d_out, int out_size) {
    const float *Dict=nullptr, *inp=nullptr, *x0=nullptr;
    for(int i=0;i<n_in;i++){
        if      (in_sizes[i]==KDIM*DDIM)  Dict=(const float*)d_in[i];
        else if (in_sizes[i]==BB*DDIM*TT) inp =(const float*)d_in[i];
        else if (in_sizes[i]==NTOT)       x0  =(const float*)d_in[i];
    }
    float* out=(float*)d_out;

    k_init<<<(NTOT+255)/256,256>>>(x0);
    k_dtd<<<KDIM,KDIM>>>(Dict);
    for(int s=0;s<NSQ;s++) k_square<<<KDIM,KDIM>>>(s);
    k_rayleigh<<<1,KDIM>>>((NSQ-1)&1);
    k_buildAt<<<KDIM,KDIM>>>();
    k_dty<<<dim3(TT/64, KDIM/64, BB),256>>>(Dict, inp);

    float mom=1.f;
    for(int it=0; it<NITER; it++){
        k_gemm_prox<<<dim3(TT/64, KDIM/64, BB),256>>>(it);
        float nm = 0.5f + 0.5f*sqrtf(1.f + 4.f*mom*mom);
        float coef = (mom-1.f)/nm;
        mom = nm;
        k_update<<<NTOT/4/256,256>>>(it, coef, out, (it==NITER-1)?1:0);
    }
}